// round 14
// baseline (speedup 1.0000x reference)
#include <cuda_runtime.h>
#include <cuda_bf16.h>
#include <math.h>

// Problem constants
#define Bsz 2
#define Sq  2048
#define Dm  2048
#define Hh  32
#define KVH 8
#define DH  64
#define ROWS (Bsz*Sq)  // 4096
#define QC  (Hh*DH)    // 2048
#define KC  (KVH*DH)   // 512

// Scratch buffers
__device__ float    g_Q [(size_t)ROWS * QC];
__device__ float    g_K [(size_t)ROWS * KC];
__device__ float    g_V [(size_t)ROWS * KC];
__device__ float    g_O [(size_t)ROWS * QC];
__device__ unsigned g_h32 [(size_t)ROWS * Dm];
__device__ unsigned g_wq32[(size_t)QC * Dm];
__device__ unsigned g_wk32[(size_t)KC * Dm];
__device__ unsigned g_wv32[(size_t)KC * Dm];
__device__ unsigned g_wo32[(size_t)Dm * Dm];
__device__ unsigned g_Vt32[(size_t)Bsz * KC * Sq];  // V transposed, tf32

__device__ __forceinline__ unsigned f2tf32(float x) {
    unsigned r;
    asm("cvt.rna.tf32.f32 %0, %1;" : "=r"(r) : "f"(x));
    return r;
}

__device__ __forceinline__ uint4 cvt4(float4 v) {
    return make_uint4(f2tf32(v.x), f2tf32(v.y), f2tf32(v.z), f2tf32(v.w));
}

__device__ __forceinline__ unsigned s2u(const void* p) {
    return (unsigned)__cvta_generic_to_shared(p);
}

__device__ __forceinline__ void cp16(unsigned saddr, const void* gptr) {
    asm volatile("cp.async.cg.shared.global [%0], [%1], 16;"
                 :: "r"(saddr), "l"(gptr));
}
#define CP_COMMIT() asm volatile("cp.async.commit_group;")
#define CP_WAIT1()  asm volatile("cp.async.wait_group 1;")
#define CP_WAIT2()  asm volatile("cp.async.wait_group 2;")

__device__ __forceinline__ void ldsm4(unsigned& r0, unsigned& r1,
                                      unsigned& r2, unsigned& r3,
                                      unsigned saddr) {
    asm volatile(
        "ldmatrix.sync.aligned.m8n8.x4.shared.b16 {%0,%1,%2,%3}, [%4];"
        : "=r"(r0), "=r"(r1), "=r"(r2), "=r"(r3) : "r"(saddr));
}

__device__ __forceinline__ void mma_tf32(float* c, const unsigned* a,
                                         unsigned b0, unsigned b1) {
    asm volatile(
        "mma.sync.aligned.m16n8k8.row.col.f32.tf32.tf32.f32 "
        "{%0,%1,%2,%3}, {%4,%5,%6,%7}, {%8,%9}, {%0,%1,%2,%3};\n"
        : "+f"(c[0]), "+f"(c[1]), "+f"(c[2]), "+f"(c[3])
        : "r"(a[0]), "r"(a[1]), "r"(a[2]), "r"(a[3]), "r"(b0), "r"(b1));
}

// ---------------------------------------------------------------------------
// Elementwise float -> tf32-bit conversion (one launch per buffer)
// ---------------------------------------------------------------------------
__global__ void cvt_tf32_kernel(const float4* __restrict__ src,
                                uint4* __restrict__ dst, int n4)
{
    int i = blockIdx.x * blockDim.x + threadIdx.x;
    if (i < n4) dst[i] = cvt4(src[i]);
}

// ---------------------------------------------------------------------------
// V transpose (per batch): [Sq][KC] -> [KC][Sq], tf32-rounded
// ---------------------------------------------------------------------------
__global__ void transpose_v_kernel(const float* __restrict__ V,
                                   unsigned* __restrict__ Vt)
{
    __shared__ float tile[32][33];
    int b  = blockIdx.z;
    int s0 = blockIdx.x * 32;
    int c0 = blockIdx.y * 32;
    int x = threadIdx.x, y = threadIdx.y;  // 32x8
#pragma unroll
    for (int i = 0; i < 4; i++)
        tile[y + 8 * i][x] = V[(size_t)(b * Sq + s0 + y + 8 * i) * KC + c0 + x];
    __syncthreads();
#pragma unroll
    for (int i = 0; i < 4; i++)
        Vt[(size_t)(b * KC + c0 + y + 8 * i) * Sq + s0 + x] =
            f2tf32(tile[x][y + 8 * i]);
}

// ---------------------------------------------------------------------------
// tf32 GEMM, 4-stage cp.async pipeline (wait_group 2), BK=16, ldmatrix frags.
// Identical structure to the proven 3-stage version; only depth changed.
// ---------------------------------------------------------------------------
#define SSTR 20
#define GEMM_STG_WORDS (128 * SSTR)
#define GEMM_STAGES 4
#define GEMM_SMEM_BYTES (2 * GEMM_STAGES * GEMM_STG_WORDS * 4)   // 81920

__device__ __forceinline__ void gemm_issue(
    unsigned* As, unsigned* Bs,
    const unsigned* A, const unsigned* B, int K, int row0, int col0,
    const int* rr, const int* kk, int kc)
{
#pragma unroll
    for (int it = 0; it < 2; it++) {
        cp16(s2u(&As[rr[it] * SSTR + kk[it]]),
             A + (size_t)(row0 + rr[it]) * K + kc + kk[it]);
        cp16(s2u(&Bs[rr[it] * SSTR + kk[it]]),
             B + (size_t)(col0 + rr[it]) * K + kc + kk[it]);
    }
}

__device__ __forceinline__ void gemm_tile_u(
    const unsigned* __restrict__ A, const unsigned* __restrict__ B,
    float* __restrict__ C, int N, int K, int row0, int col0)
{
    extern __shared__ unsigned gsm[];
    unsigned* Asb = gsm;                        // [4][GEMM_STG_WORDS]
    unsigned* Bsb = gsm + GEMM_STAGES * GEMM_STG_WORDS;

    const int tid  = threadIdx.x;
    const int wid  = tid >> 5;
    const int lane = tid & 31;
    const int g    = lane >> 2;
    const int t    = lane & 3;
    const int wm   = wid & 1;
    const int wn   = wid >> 1;

    const int rowA = (lane & 7) + ((lane >> 3) & 1) * 8;
    const int colA = (lane >> 4) * 4;
    const int rowB = (lane & 7) + (lane >> 4) * 8;
    const int colB = ((lane >> 3) & 1) * 4;

    int rr[2], kk[2];
#pragma unroll
    for (int it = 0; it < 2; it++) {
        int idx = tid + it * 256;
        rr[it] = idx >> 2;
        kk[it] = (idx & 3) * 4;
    }

    // Prologue: fill stages 0..2 (tiles kc = 0, 16, 32)
    gemm_issue(Asb, Bsb, A, B, K, row0, col0, rr, kk, 0);
    CP_COMMIT();
    gemm_issue(Asb + GEMM_STG_WORDS, Bsb + GEMM_STG_WORDS,
               A, B, K, row0, col0, rr, kk, 16);
    CP_COMMIT();
    gemm_issue(Asb + 2 * GEMM_STG_WORDS, Bsb + 2 * GEMM_STG_WORDS,
               A, B, K, row0, col0, rr, kk, 32);
    CP_COMMIT();

    float c[4][4][4];
#pragma unroll
    for (int mt = 0; mt < 4; mt++)
#pragma unroll
        for (int nt = 0; nt < 4; nt++)
#pragma unroll
            for (int i = 0; i < 4; i++) c[mt][nt][i] = 0.f;

    int s = 0;
    for (int kc = 0; kc < K; kc += 16) {
        CP_WAIT2();
        __syncthreads();

        int kn = kc + 48;
        int sn = s + 3; if (sn >= GEMM_STAGES) sn -= GEMM_STAGES;
        if (kn < K)
            gemm_issue(Asb + sn * GEMM_STG_WORDS, Bsb + sn * GEMM_STG_WORDS,
                       A, B, K, row0, col0, rr, kk, kn);
        CP_COMMIT();

        unsigned* As = Asb + s * GEMM_STG_WORDS;
        unsigned* Bs = Bsb + s * GEMM_STG_WORDS;
#pragma unroll
        for (int ks = 0; ks < 16; ks += 8) {
            unsigned a[4][4], bf[4][2];
#pragma unroll
            for (int mt = 0; mt < 4; mt++)
                ldsm4(a[mt][0], a[mt][1], a[mt][2], a[mt][3],
                      s2u(&As[(wm * 64 + mt * 16 + rowA) * SSTR + ks + colA]));
#pragma unroll
            for (int p = 0; p < 2; p++) {
                unsigned r0, r1, r2, r3;
                ldsm4(r0, r1, r2, r3,
                      s2u(&Bs[(wn * 32 + p * 16 + rowB) * SSTR + ks + colB]));
                bf[2 * p][0] = r0; bf[2 * p][1] = r1;
                bf[2 * p + 1][0] = r2; bf[2 * p + 1][1] = r3;
            }
#pragma unroll
            for (int mt = 0; mt < 4; mt++)
#pragma unroll
                for (int nt = 0; nt < 4; nt++)
                    mma_tf32(c[mt][nt], a[mt], bf[nt][0], bf[nt][1]);
        }
        s = (s + 1 == GEMM_STAGES) ? 0 : s + 1;
        __syncthreads();
    }

#pragma unroll
    for (int mt = 0; mt < 4; mt++) {
#pragma unroll
        for (int nt = 0; nt < 4; nt++) {
            int r  = row0 + wm * 64 + mt * 16 + g;
            int cc = col0 + wn * 32 + nt * 8 + 2 * t;
            float2 lo = make_float2(c[mt][nt][0], c[mt][nt][1]);
            float2 hi = make_float2(c[mt][nt][2], c[mt][nt][3]);
            *(float2*)&C[(size_t)r * N + cc]       = lo;
            *(float2*)&C[(size_t)(r + 8) * N + cc] = hi;
        }
    }
}

__global__ __launch_bounds__(256, 2) void qkv_gemm(
    const unsigned* __restrict__ hidden,
    const unsigned* __restrict__ Wq, const unsigned* __restrict__ Wk,
    const unsigned* __restrict__ Wv,
    float* __restrict__ Qb, float* __restrict__ Kb, float* __restrict__ Vb)
{
    const int bx = blockIdx.x;
    const unsigned* B;
    float* C;
    int Nc, col0;
    if (bx < 16)      { B = Wq; C = Qb; Nc = QC; col0 = bx * 128; }
    else if (bx < 20) { B = Wk; C = Kb; Nc = KC; col0 = (bx - 16) * 128; }
    else              { B = Wv; C = Vb; Nc = KC; col0 = (bx - 20) * 128; }
    gemm_tile_u(hidden, B, C, Nc, Dm, blockIdx.y * 128, col0);
}

__global__ __launch_bounds__(256, 2) void out_gemm(
    const unsigned* __restrict__ A, const unsigned* __restrict__ B,
    float* __restrict__ C)
{
    gemm_tile_u(A, B, C, Dm, Dm, blockIdx.y * 128, blockIdx.x * 128);
}

// ---------------------------------------------------------------------------
// Merged in-place RoPE over Q then K (one launch)
// ---------------------------------------------------------------------------
#define PQ (ROWS * (QC / 2))
#define PK (ROWS * (KC / 2))

__global__ void rope_both_kernel(float* __restrict__ Qb, float* __restrict__ Kb,
                                 const float* __restrict__ cosb,
                                 const float* __restrict__ sinb)
{
    int idx = blockIdx.x * blockDim.x + threadIdx.x;
    float* X;
    int C;
    if (idx < PQ) {
        X = Qb; C = QC;
    } else {
        idx -= PQ;
        if (idx >= PK) return;
        X = Kb; C = KC;
    }
    int per_row = C >> 1;
    int row  = idx / per_row;
    int p    = idx - row * per_row;
    int head = p >> 5;
    int d    = p & 31;
    int col1 = head * 64 + d;
    int col2 = col1 + 32;

    float c1 = cosb[row * 64 + d];
    float s1 = sinb[row * 64 + d];
    float c2 = cosb[row * 64 + d + 32];
    float s2 = sinb[row * 64 + d + 32];

    size_t base = (size_t)row * C;
    float x1 = X[base + col1];
    float x2 = X[base + col2];
    X[base + col1] = __uint_as_float(f2tf32(x1 * c1 - x2 * s1));
    X[base + col2] = __uint_as_float(f2tf32(x2 * c2 + x1 * s2));
}

// ---------------------------------------------------------------------------
// Flash attention (round-9 flash8, exact): tf32, ldmatrix, 256-row q tile,
// 32 rows/warp, double-buffered cp.async K/V, pre-roped tf32 Q.
// ---------------------------------------------------------------------------
#define QT  256
#define FST 68
#define FLASH_SMEM_WORDS ((2 * QT + 4 * 64) * FST)   // 208896 B

__global__ __launch_bounds__(256, 1) void flash_kernel(
    const unsigned* __restrict__ Q, const unsigned* __restrict__ K,
    const unsigned* __restrict__ Vt_g, float* __restrict__ O)
{
    const int qt2 = (Sq / QT - 1) - blockIdx.x;   // big blocks first
    const int h   = blockIdx.y;
    const int b   = blockIdx.z;
    const int kvh = h >> 2;

    extern __shared__ unsigned smu[];
    unsigned* Qs  = smu;                          // QT*FST
    unsigned* Ps  = smu + QT * FST;               // QT*FST
    unsigned* Ksb = smu + 2 * QT * FST;           // 2 stages x 64*FST
    unsigned* Vtb = smu + 2 * QT * FST + 2 * 64 * FST;

    const int tid  = threadIdx.x;
    const int w    = tid >> 5;
    const int lane = tid & 31;
    const int g    = lane >> 2;
    const int t    = lane & 3;
    const int q0   = qt2 * QT;
    const int wb   = w * 32;

    const int rowA = (lane & 7) + ((lane >> 3) & 1) * 8;
    const int colA = (lane >> 4) * 4;
    const int rowB = (lane & 7) + (lane >> 4) * 8;
    const int colB = ((lane >> 3) & 1) * 4;

    const int lr = tid >> 2;
    const int cb = (tid & 3) * 16;

    const unsigned* Kbase  = K    + (size_t)(b * Sq) * KC + kvh * DH;
    const unsigned* Vtbase = Vt_g + ((size_t)b * KC + kvh * DH + lr) * Sq;

    // Prologue: issue tile kt=0 into stage 0
    {
        const unsigned* kg = Kbase + (size_t)lr * KC + cb;
#pragma unroll
        for (int i = 0; i < 4; i++)
            cp16(s2u(&Ksb[lr * FST + cb + i * 4]), kg + i * 4);
        const unsigned* vg = Vtbase + cb;
#pragma unroll
        for (int i = 0; i < 4; i++)
            cp16(s2u(&Vtb[lr * FST + cb + i * 4]), vg + i * 4);
    }
    CP_COMMIT();

    // Load Q tile (QT rows): one row per thread, pre-converted, vectorized
    {
        const unsigned* qg = Q + (size_t)(b * Sq + q0 + tid) * QC + h * DH;
#pragma unroll
        for (int i = 0; i < 16; i++)
            *(uint4*)&Qs[tid * FST + i * 4] = *(const uint4*)(qg + i * 4);
    }

    float m[4], l[4];
#pragma unroll
    for (int i = 0; i < 4; i++) { m[i] = -1e30f; l[i] = 0.f; }
    float acc[2][8][4];
#pragma unroll
    for (int mt = 0; mt < 2; mt++)
#pragma unroll
        for (int nt = 0; nt < 8; nt++)
#pragma unroll
            for (int i = 0; i < 4; i++) acc[mt][nt][i] = 0.f;

    const int wmax  = q0 + wb + 31;
    const int ktmax = (q0 + QT - 1) / 64;

    for (int kt = 0; kt <= ktmax; ++kt) {
        const int k0 = kt * 64;
        const int st = kt & 1;

        __syncthreads();

        if (kt < ktmax) {
            const int kn = k0 + 64;
            const unsigned* kg = Kbase + (size_t)(kn + lr) * KC + cb;
            unsigned* Ksn = Ksb + (st ^ 1) * 64 * FST;
            unsigned* Vtn = Vtb + (st ^ 1) * 64 * FST;
#pragma unroll
            for (int i = 0; i < 4; i++)
                cp16(s2u(&Ksn[lr * FST + cb + i * 4]), kg + i * 4);
            const unsigned* vg = Vtbase + kn + cb;
#pragma unroll
            for (int i = 0; i < 4; i++)
                cp16(s2u(&Vtn[lr * FST + cb + i * 4]), vg + i * 4);
        }
        CP_COMMIT();
        CP_WAIT1();
        __syncthreads();

        if (k0 > wmax) continue;

        unsigned* Ks = Ksb + st * 64 * FST;
        unsigned* Vt = Vtb + st * 64 * FST;

        // ---- S = Q K^T ----
        float sc[2][8][4];
#pragma unroll
        for (int mt = 0; mt < 2; mt++)
#pragma unroll
            for (int nt = 0; nt < 8; nt++)
#pragma unroll
                for (int i = 0; i < 4; i++) sc[mt][nt][i] = 0.f;

#pragma unroll
        for (int ks = 0; ks < 8; ks++) {
            unsigned a[2][4];
#pragma unroll
            for (int mt = 0; mt < 2; mt++)
                ldsm4(a[mt][0], a[mt][1], a[mt][2], a[mt][3],
                      s2u(&Qs[(wb + mt * 16 + rowA) * FST + ks * 8 + colA]));
#pragma unroll
            for (int p = 0; p < 4; p++) {
                unsigned b0, b1, b2, b3;
                ldsm4(b0, b1, b2, b3,
                      s2u(&Ks[(p * 16 + rowB) * FST + ks * 8 + colB]));
#pragma unroll
                for (int mt = 0; mt < 2; mt++) {
                    mma_tf32(sc[mt][2 * p],     a[mt], b0, b1);
                    mma_tf32(sc[mt][2 * p + 1], a[mt], b2, b3);
                }
            }
        }

        // ---- softmax ----
#pragma unroll
        for (int mt = 0; mt < 2; mt++) {
            const int rlo = q0 + wb + mt * 16 + g;
            const int rhi = rlo + 8;
            const bool need_mask = (k0 + 63 > rlo);
            float rmax0 = -1e30f, rmax1 = -1e30f;
#pragma unroll
            for (int nt = 0; nt < 8; nt++) {
#pragma unroll
                for (int c2 = 0; c2 < 2; c2++) {
                    float v0 = sc[mt][nt][c2    ] * 0.125f;
                    float v1 = sc[mt][nt][c2 + 2] * 0.125f;
                    if (need_mask) {
                        int kj = k0 + nt * 8 + 2 * t + c2;
                        if (kj > rlo) v0 = -1e30f;
                        if (kj > rhi) v1 = -1e30f;
                    }
                    sc[mt][nt][c2    ] = v0;
                    sc[mt][nt][c2 + 2] = v1;
                    rmax0 = fmaxf(rmax0, v0);
                    rmax1 = fmaxf(rmax1, v1);
                }
            }
            rmax0 = fmaxf(rmax0, __shfl_xor_sync(0xffffffffu, rmax0, 1));
            rmax0 = fmaxf(rmax0, __shfl_xor_sync(0xffffffffu, rmax0, 2));
            rmax1 = fmaxf(rmax1, __shfl_xor_sync(0xffffffffu, rmax1, 1));
            rmax1 = fmaxf(rmax1, __shfl_xor_sync(0xffffffffu, rmax1, 2));

            float mn0 = fmaxf(m[mt * 2],     rmax0);
            float mn1 = fmaxf(m[mt * 2 + 1], rmax1);
            float corr0 = __expf(m[mt * 2]     - mn0);
            float corr1 = __expf(m[mt * 2 + 1] - mn1);
            m[mt * 2] = mn0; m[mt * 2 + 1] = mn1;

            float ls0 = 0.f, ls1 = 0.f;
#pragma unroll
            for (int nt = 0; nt < 8; nt++) {
#pragma unroll
                for (int c2 = 0; c2 < 2; c2++) {
                    float p0 = __expf(sc[mt][nt][c2    ] - mn0);
                    float p1 = __expf(sc[mt][nt][c2 + 2] - mn1);
                    ls0 += p0; ls1 += p1;
                    int jj = nt * 8 + 2 * t + c2;
                    Ps[(wb + mt * 16 + g    ) * FST + jj] = f2tf32(p0);
                    Ps[(wb + mt * 16 + g + 8) * FST + jj] = f2tf32(p1);
                }
            }
            ls0 += __shfl_xor_sync(0xffffffffu, ls0, 1);
            ls0 += __shfl_xor_sync(0xffffffffu, ls0, 2);
            ls1 += __shfl_xor_sync(0xffffffffu, ls1, 1);
            ls1 += __shfl_xor_sync(0xffffffffu, ls1, 2);
            l[mt * 2]     = l[mt * 2]     * corr0 + ls0;
            l[mt * 2 + 1] = l[mt * 2 + 1] * corr1 + ls1;

#pragma unroll
            for (int nt = 0; nt < 8; nt++) {
                acc[mt][nt][0] *= corr0; acc[mt][nt][1] *= corr0;
                acc[mt][nt][2] *= corr1; acc[mt][nt][3] *= corr1;
            }
        }

        __syncwarp();

        // ---- acc += P V ----
#pragma unroll
        for (int ks = 0; ks < 8; ks++) {
            unsigned a[2][4];
#pragma unroll
            for (int mt = 0; mt < 2; mt++)
                ldsm4(a[mt][0], a[mt][1], a[mt][2], a[mt][3],
                      s2u(&Ps[(wb + mt * 16 + rowA) * FST + ks * 8 + colA]));
#pragma unroll
            for (int p = 0; p < 4; p++) {
                unsigned b0, b1, b2, b3;
                ldsm4(b0, b1, b2, b3,
                      s2u(&Vt[(p * 16 + rowB) * FST + ks * 8 + colB]));
#pragma unroll
                for (int mt = 0; mt < 2; mt++) {
                    mma_tf32(acc[mt][2 * p],     a[mt], b0, b1);
                    mma_tf32(acc[mt][2 * p + 1], a[mt], b2, b3);
                }
            }
        }
    }

    // Epilogue (tf32-rounded)
#pragma unroll
    for (int mt = 0; mt < 2; mt++) {
        float inv0 = 1.f / l[mt * 2];
        float inv1 = 1.f / l[mt * 2 + 1];
        size_t orow0 = (size_t)(b * Sq + q0 + wb + mt * 16 + g) * QC;
        size_t orow1 = orow0 + 8 * (size_t)QC;
#pragma unroll
        for (int nt = 0; nt < 8; nt++) {
            int col = h * DH + nt * 8 + 2 * t;
            float2 lo = make_float2(
                __uint_as_float(f2tf32(acc[mt][nt][0] * inv0)),
                __uint_as_float(f2tf32(acc[mt][nt][1] * inv0)));
            float2 hi = make_float2(
                __uint_as_float(f2tf32(acc[mt][nt][2] * inv1)),
                __uint_as_float(f2tf32(acc[mt][nt][3] * inv1)));
            *(float2*)&O[orow0 + col] = lo;
            *(float2*)&O[orow1 + col] = hi;
        }
    }
}

// ---------------------------------------------------------------------------
// kernel_launch
// ---------------------------------------------------------------------------
extern "C" void kernel_launch(void* const* d_in, const int* in_sizes, int n_in,
                              void* d_out, int out_size)
{
    const float* hidden = (const float*)d_in[0];
    const float* cosb   = (const float*)d_in[1];
    const float* sinb   = (const float*)d_in[2];
    const float* Wq     = (const float*)d_in[4];
    const float* Wk     = (const float*)d_in[5];
    const float* Wv     = (const float*)d_in[6];
    const float* Wo     = (const float*)d_in[7];
    float* out = (float*)d_out;

    float *Qb, *Kb, *Vb, *Ob;
    unsigned *h32, *wq32, *wk32, *wv32, *wo32, *vt32;
    cudaGetSymbolAddress((void**)&Qb, g_Q);
    cudaGetSymbolAddress((void**)&Kb, g_K);
    cudaGetSymbolAddress((void**)&Vb, g_V);
    cudaGetSymbolAddress((void**)&Ob, g_O);
    cudaGetSymbolAddress((void**)&h32,  g_h32);
    cudaGetSymbolAddress((void**)&wq32, g_wq32);
    cudaGetSymbolAddress((void**)&wk32, g_wk32);
    cudaGetSymbolAddress((void**)&wv32, g_wv32);
    cudaGetSymbolAddress((void**)&wo32, g_wo32);
    cudaGetSymbolAddress((void**)&vt32, g_Vt32);

    // Pre-convert inputs to tf32 bit patterns (5 launches, round-9 form)
    {
        struct { const float* s; unsigned* d; size_t n; } jobs[5] = {
            { hidden, h32,  (size_t)ROWS * Dm },
            { Wq,     wq32, (size_t)QC * Dm },
            { Wk,     wk32, (size_t)KC * Dm },
            { Wv,     wv32, (size_t)KC * Dm },
            { Wo,     wo32, (size_t)Dm * Dm },
        };
        for (int j = 0; j < 5; j++) {
            int n4 = (int)(jobs[j].n / 4);
            cvt_tf32_kernel<<<(n4 + 255) / 256, 256>>>(
                (const float4*)jobs[j].s, (uint4*)jobs[j].d, n4);
        }
    }

    // Fused QKV projections (4-stage BK=16 cp.async pipeline)
    cudaFuncSetAttribute(qkv_gemm,
        cudaFuncAttributeMaxDynamicSharedMemorySize, GEMM_SMEM_BYTES);
    qkv_gemm<<<dim3(24, ROWS / 128), 256, GEMM_SMEM_BYTES>>>(
        h32, wq32, wk32, wv32, Qb, Kb, Vb);

    // RoPE on Q and K (single merged launch)
    {
        int total = PQ + PK;
        rope_both_kernel<<<(total + 255) / 256, 256>>>(Qb, Kb, cosb, sinb);
    }

    // Transpose V to [KC][Sq], tf32
    transpose_v_kernel<<<dim3(Sq / 32, KC / 32, Bsz), dim3(32, 8)>>>(Vb, vt32);

    // Flash attention (tf32, double-buffered cp.async K/V)
    {
        int smem_bytes = FLASH_SMEM_WORDS * (int)sizeof(unsigned);  // 208896
        cudaFuncSetAttribute(flash_kernel,
            cudaFuncAttributeMaxDynamicSharedMemorySize, smem_bytes);
        dim3 grid(Sq / QT, Hh, Bsz);
        flash_kernel<<<grid, 256, smem_bytes>>>(
            (const unsigned*)Qb, (const unsigned*)Kb, vt32, Ob);
    }

    // Output projection
    cudaFuncSetAttribute(out_gemm,
        cudaFuncAttributeMaxDynamicSharedMemorySize, GEMM_SMEM_BYTES);
    out_gemm<<<dim3(Dm / 128, ROWS / 128), 256, GEMM_SMEM_BYTES>>>(
        (const unsigned*)Ob, wo32, out);
}

// round 16
// speedup vs baseline: 1.1979x; 1.1979x over previous
#include <cuda_runtime.h>
#include <cuda_bf16.h>
#include <math.h>

// Problem constants
#define Bsz 2
#define Sq  2048
#define Dm  2048
#define Hh  32
#define KVH 8
#define DH  64
#define ROWS (Bsz*Sq)  // 4096
#define QC  (Hh*DH)    // 2048
#define KC  (KVH*DH)   // 512

// Scratch buffers
__device__ float    g_Q [(size_t)ROWS * QC];
__device__ float    g_K [(size_t)ROWS * KC];
__device__ float    g_V [(size_t)ROWS * KC];
__device__ float    g_O [(size_t)ROWS * QC];
__device__ unsigned g_h32 [(size_t)ROWS * Dm];
__device__ unsigned g_wq32[(size_t)QC * Dm];
__device__ unsigned g_wk32[(size_t)KC * Dm];
__device__ unsigned g_wv32[(size_t)KC * Dm];
__device__ unsigned g_wo32[(size_t)Dm * Dm];
__device__ unsigned g_Vt32[(size_t)Bsz * KC * Sq];  // V transposed, tf32

__device__ __forceinline__ unsigned f2tf32(float x) {
    unsigned r;
    asm("cvt.rna.tf32.f32 %0, %1;" : "=r"(r) : "f"(x));
    return r;
}

__device__ __forceinline__ uint4 cvt4(float4 v) {
    return make_uint4(f2tf32(v.x), f2tf32(v.y), f2tf32(v.z), f2tf32(v.w));
}

__device__ __forceinline__ unsigned s2u(const void* p) {
    return (unsigned)__cvta_generic_to_shared(p);
}

__device__ __forceinline__ void cp16(unsigned saddr, const void* gptr) {
    asm volatile("cp.async.cg.shared.global [%0], [%1], 16;"
                 :: "r"(saddr), "l"(gptr));
}
#define CP_COMMIT() asm volatile("cp.async.commit_group;")
#define CP_WAIT1()  asm volatile("cp.async.wait_group 1;")

__device__ __forceinline__ void ldsm4(unsigned& r0, unsigned& r1,
                                      unsigned& r2, unsigned& r3,
                                      unsigned saddr) {
    asm volatile(
        "ldmatrix.sync.aligned.m8n8.x4.shared.b16 {%0,%1,%2,%3}, [%4];"
        : "=r"(r0), "=r"(r1), "=r"(r2), "=r"(r3) : "r"(saddr));
}

__device__ __forceinline__ void mma_tf32(float* c, const unsigned* a,
                                         unsigned b0, unsigned b1) {
    asm volatile(
        "mma.sync.aligned.m16n8k8.row.col.f32.tf32.tf32.f32 "
        "{%0,%1,%2,%3}, {%4,%5,%6,%7}, {%8,%9}, {%0,%1,%2,%3};\n"
        : "+f"(c[0]), "+f"(c[1]), "+f"(c[2]), "+f"(c[3])
        : "r"(a[0]), "r"(a[1]), "r"(a[2]), "r"(a[3]), "r"(b0), "r"(b1));
}

// ---------------------------------------------------------------------------
// Elementwise float -> tf32-bit conversion (one launch per buffer)
// ---------------------------------------------------------------------------
__global__ void cvt_tf32_kernel(const float4* __restrict__ src,
                                uint4* __restrict__ dst, int n4)
{
    int i = blockIdx.x * blockDim.x + threadIdx.x;
    if (i < n4) dst[i] = cvt4(src[i]);
}

// ---------------------------------------------------------------------------
// V transpose (per batch): [Sq][KC] -> [KC][Sq], tf32-rounded
// ---------------------------------------------------------------------------
__global__ void transpose_v_kernel(const float* __restrict__ V,
                                   unsigned* __restrict__ Vt)
{
    __shared__ float tile[32][33];
    int b  = blockIdx.z;
    int s0 = blockIdx.x * 32;
    int c0 = blockIdx.y * 32;
    int x = threadIdx.x, y = threadIdx.y;  // 32x8
#pragma unroll
    for (int i = 0; i < 4; i++)
        tile[y + 8 * i][x] = V[(size_t)(b * Sq + s0 + y + 8 * i) * KC + c0 + x];
    __syncthreads();
#pragma unroll
    for (int i = 0; i < 4; i++)
        Vt[(size_t)(b * KC + c0 + y + 8 * i) * Sq + s0 + x] =
            f2tf32(tile[x][y + 8 * i]);
}

// ---------------------------------------------------------------------------
// tf32 GEMM, 3-stage cp.async pipeline, BK=16, ldmatrix frags.
// ROUND-15 CHANGE: 4 warps / 128 threads, warp tile 64x64
// (was 8 warps x 64x32) -> 32 MMAs per 8 ldsm4, 2x ILP per warp.
// Pipeline structure identical to the proven round-9/13 version.
// ---------------------------------------------------------------------------
#define SSTR 20
#define GEMM_STG_WORDS (128 * SSTR)
#define GEMM_SMEM_BYTES (2 * 3 * GEMM_STG_WORDS * 4)   // 61440
#define GEMM_THREADS 128

__device__ __forceinline__ void gemm_issue(
    unsigned* As, unsigned* Bs,
    const unsigned* A, const unsigned* B, int K, int row0, int col0,
    const int* rr, const int* kk, int kc)
{
#pragma unroll
    for (int it = 0; it < 4; it++) {
        cp16(s2u(&As[rr[it] * SSTR + kk[it]]),
             A + (size_t)(row0 + rr[it]) * K + kc + kk[it]);
        cp16(s2u(&Bs[rr[it] * SSTR + kk[it]]),
             B + (size_t)(col0 + rr[it]) * K + kc + kk[it]);
    }
}

__device__ __forceinline__ void gemm_tile_u(
    const unsigned* __restrict__ A, const unsigned* __restrict__ B,
    float* __restrict__ C, int N, int K, int row0, int col0)
{
    extern __shared__ unsigned gsm[];
    unsigned* Asb = gsm;                        // [3][GEMM_STG_WORDS]
    unsigned* Bsb = gsm + 3 * GEMM_STG_WORDS;

    const int tid  = threadIdx.x;
    const int wid  = tid >> 5;
    const int lane = tid & 31;
    const int g    = lane >> 2;
    const int t    = lane & 3;
    const int wm   = wid & 1;      // 0..1  (64-row half)
    const int wn   = wid >> 1;     // 0..1  (64-col half)

    const int rowA = (lane & 7) + ((lane >> 3) & 1) * 8;
    const int colA = (lane >> 4) * 4;
    const int rowB = (lane & 7) + (lane >> 4) * 8;
    const int colB = ((lane >> 3) & 1) * 4;

    int rr[4], kk[4];
#pragma unroll
    for (int it = 0; it < 4; it++) {
        int idx = tid + it * GEMM_THREADS;   // 0..511
        rr[it] = idx >> 2;
        kk[it] = (idx & 3) * 4;
    }

    gemm_issue(Asb, Bsb, A, B, K, row0, col0, rr, kk, 0);
    CP_COMMIT();
    gemm_issue(Asb + GEMM_STG_WORDS, Bsb + GEMM_STG_WORDS,
               A, B, K, row0, col0, rr, kk, 16);
    CP_COMMIT();

    float c[4][8][4];
#pragma unroll
    for (int mt = 0; mt < 4; mt++)
#pragma unroll
        for (int nt = 0; nt < 8; nt++)
#pragma unroll
            for (int i = 0; i < 4; i++) c[mt][nt][i] = 0.f;

    int s = 0;
    for (int kc = 0; kc < K; kc += 16) {
        CP_WAIT1();
        __syncthreads();

        int kn = kc + 32;
        int sn = s + 2; if (sn >= 3) sn -= 3;
        if (kn < K)
            gemm_issue(Asb + sn * GEMM_STG_WORDS, Bsb + sn * GEMM_STG_WORDS,
                       A, B, K, row0, col0, rr, kk, kn);
        CP_COMMIT();

        unsigned* As = Asb + s * GEMM_STG_WORDS;
        unsigned* Bs = Bsb + s * GEMM_STG_WORDS;
#pragma unroll
        for (int ks = 0; ks < 16; ks += 8) {
            unsigned a[4][4], bf[8][2];
#pragma unroll
            for (int mt = 0; mt < 4; mt++)
                ldsm4(a[mt][0], a[mt][1], a[mt][2], a[mt][3],
                      s2u(&As[(wm * 64 + mt * 16 + rowA) * SSTR + ks + colA]));
#pragma unroll
            for (int p = 0; p < 4; p++) {
                unsigned r0, r1, r2, r3;
                ldsm4(r0, r1, r2, r3,
                      s2u(&Bs[(wn * 64 + p * 16 + rowB) * SSTR + ks + colB]));
                bf[2 * p][0] = r0; bf[2 * p][1] = r1;
                bf[2 * p + 1][0] = r2; bf[2 * p + 1][1] = r3;
            }
#pragma unroll
            for (int mt = 0; mt < 4; mt++)
#pragma unroll
                for (int nt = 0; nt < 8; nt++)
                    mma_tf32(c[mt][nt], a[mt], bf[nt][0], bf[nt][1]);
        }
        s = (s + 1 == 3) ? 0 : s + 1;
        __syncthreads();
    }

#pragma unroll
    for (int mt = 0; mt < 4; mt++) {
#pragma unroll
        for (int nt = 0; nt < 8; nt++) {
            int r  = row0 + wm * 64 + mt * 16 + g;
            int cc = col0 + wn * 64 + nt * 8 + 2 * t;
            float2 lo = make_float2(c[mt][nt][0], c[mt][nt][1]);
            float2 hi = make_float2(c[mt][nt][2], c[mt][nt][3]);
            *(float2*)&C[(size_t)r * N + cc]       = lo;
            *(float2*)&C[(size_t)(r + 8) * N + cc] = hi;
        }
    }
}

__global__ __launch_bounds__(GEMM_THREADS, 2) void qkv_gemm(
    const unsigned* __restrict__ hidden,
    const unsigned* __restrict__ Wq, const unsigned* __restrict__ Wk,
    const unsigned* __restrict__ Wv,
    float* __restrict__ Qb, float* __restrict__ Kb, float* __restrict__ Vb)
{
    const int bx = blockIdx.x;
    const unsigned* B;
    float* C;
    int Nc, col0;
    if (bx < 16)      { B = Wq; C = Qb; Nc = QC; col0 = bx * 128; }
    else if (bx < 20) { B = Wk; C = Kb; Nc = KC; col0 = (bx - 16) * 128; }
    else              { B = Wv; C = Vb; Nc = KC; col0 = (bx - 20) * 128; }
    gemm_tile_u(hidden, B, C, Nc, Dm, blockIdx.y * 128, col0);
}

__global__ __launch_bounds__(GEMM_THREADS, 2) void out_gemm(
    const unsigned* __restrict__ A, const unsigned* __restrict__ B,
    float* __restrict__ C)
{
    gemm_tile_u(A, B, C, Dm, Dm, blockIdx.y * 128, blockIdx.x * 128);
}

// ---------------------------------------------------------------------------
// Merged in-place RoPE over Q then K (one launch)
// ---------------------------------------------------------------------------
#define PQ (ROWS * (QC / 2))
#define PK (ROWS * (KC / 2))

__global__ void rope_both_kernel(float* __restrict__ Qb, float* __restrict__ Kb,
                                 const float* __restrict__ cosb,
                                 const float* __restrict__ sinb)
{
    int idx = blockIdx.x * blockDim.x + threadIdx.x;
    float* X;
    int C;
    if (idx < PQ) {
        X = Qb; C = QC;
    } else {
        idx -= PQ;
        if (idx >= PK) return;
        X = Kb; C = KC;
    }
    int per_row = C >> 1;
    int row  = idx / per_row;
    int p    = idx - row * per_row;
    int head = p >> 5;
    int d    = p & 31;
    int col1 = head * 64 + d;
    int col2 = col1 + 32;

    float c1 = cosb[row * 64 + d];
    float s1 = sinb[row * 64 + d];
    float c2 = cosb[row * 64 + d + 32];
    float s2 = sinb[row * 64 + d + 32];

    size_t base = (size_t)row * C;
    float x1 = X[base + col1];
    float x2 = X[base + col2];
    X[base + col1] = __uint_as_float(f2tf32(x1 * c1 - x2 * s1));
    X[base + col2] = __uint_as_float(f2tf32(x2 * c2 + x1 * s2));
}

// ---------------------------------------------------------------------------
// Flash attention (round-9 flash8, exact): tf32, ldmatrix, 256-row q tile,
// 32 rows/warp, double-buffered cp.async K/V, pre-roped tf32 Q.
// ---------------------------------------------------------------------------
#define QT  256
#define FST 68
#define FLASH_SMEM_WORDS ((2 * QT + 4 * 64) * FST)   // 208896 B

__global__ __launch_bounds__(256, 1) void flash_kernel(
    const unsigned* __restrict__ Q, const unsigned* __restrict__ K,
    const unsigned* __restrict__ Vt_g, float* __restrict__ O)
{
    const int qt2 = (Sq / QT - 1) - blockIdx.x;   // big blocks first
    const int h   = blockIdx.y;
    const int b   = blockIdx.z;
    const int kvh = h >> 2;

    extern __shared__ unsigned smu[];
    unsigned* Qs  = smu;                          // QT*FST
    unsigned* Ps  = smu + QT * FST;               // QT*FST
    unsigned* Ksb = smu + 2 * QT * FST;           // 2 stages x 64*FST
    unsigned* Vtb = smu + 2 * QT * FST + 2 * 64 * FST;

    const int tid  = threadIdx.x;
    const int w    = tid >> 5;
    const int lane = tid & 31;
    const int g    = lane >> 2;
    const int t    = lane & 3;
    const int q0   = qt2 * QT;
    const int wb   = w * 32;

    const int rowA = (lane & 7) + ((lane >> 3) & 1) * 8;
    const int colA = (lane >> 4) * 4;
    const int rowB = (lane & 7) + (lane >> 4) * 8;
    const int colB = ((lane >> 3) & 1) * 4;

    const int lr = tid >> 2;
    const int cb = (tid & 3) * 16;

    const unsigned* Kbase  = K    + (size_t)(b * Sq) * KC + kvh * DH;
    const unsigned* Vtbase = Vt_g + ((size_t)b * KC + kvh * DH + lr) * Sq;

    // Prologue: issue tile kt=0 into stage 0
    {
        const unsigned* kg = Kbase + (size_t)lr * KC + cb;
#pragma unroll
        for (int i = 0; i < 4; i++)
            cp16(s2u(&Ksb[lr * FST + cb + i * 4]), kg + i * 4);
        const unsigned* vg = Vtbase + cb;
#pragma unroll
        for (int i = 0; i < 4; i++)
            cp16(s2u(&Vtb[lr * FST + cb + i * 4]), vg + i * 4);
    }
    CP_COMMIT();

    // Load Q tile (QT rows): one row per thread, pre-converted, vectorized
    {
        const unsigned* qg = Q + (size_t)(b * Sq + q0 + tid) * QC + h * DH;
#pragma unroll
        for (int i = 0; i < 16; i++)
            *(uint4*)&Qs[tid * FST + i * 4] = *(const uint4*)(qg + i * 4);
    }

    float m[4], l[4];
#pragma unroll
    for (int i = 0; i < 4; i++) { m[i] = -1e30f; l[i] = 0.f; }
    float acc[2][8][4];
#pragma unroll
    for (int mt = 0; mt < 2; mt++)
#pragma unroll
        for (int nt = 0; nt < 8; nt++)
#pragma unroll
            for (int i = 0; i < 4; i++) acc[mt][nt][i] = 0.f;

    const int wmax  = q0 + wb + 31;
    const int ktmax = (q0 + QT - 1) / 64;

    for (int kt = 0; kt <= ktmax; ++kt) {
        const int k0 = kt * 64;
        const int st = kt & 1;

        __syncthreads();

        if (kt < ktmax) {
            const int kn = k0 + 64;
            const unsigned* kg = Kbase + (size_t)(kn + lr) * KC + cb;
            unsigned* Ksn = Ksb + (st ^ 1) * 64 * FST;
            unsigned* Vtn = Vtb + (st ^ 1) * 64 * FST;
#pragma unroll
            for (int i = 0; i < 4; i++)
                cp16(s2u(&Ksn[lr * FST + cb + i * 4]), kg + i * 4);
            const unsigned* vg = Vtbase + kn + cb;
#pragma unroll
            for (int i = 0; i < 4; i++)
                cp16(s2u(&Vtn[lr * FST + cb + i * 4]), vg + i * 4);
        }
        CP_COMMIT();
        CP_WAIT1();
        __syncthreads();

        if (k0 > wmax) continue;

        unsigned* Ks = Ksb + st * 64 * FST;
        unsigned* Vt = Vtb + st * 64 * FST;

        // ---- S = Q K^T ----
        float sc[2][8][4];
#pragma unroll
        for (int mt = 0; mt < 2; mt++)
#pragma unroll
            for (int nt = 0; nt < 8; nt++)
#pragma unroll
                for (int i = 0; i < 4; i++) sc[mt][nt][i] = 0.f;

#pragma unroll
        for (int ks = 0; ks < 8; ks++) {
            unsigned a[2][4];
#pragma unroll
            for (int mt = 0; mt < 2; mt++)
                ldsm4(a[mt][0], a[mt][1], a[mt][2], a[mt][3],
                      s2u(&Qs[(wb + mt * 16 + rowA) * FST + ks * 8 + colA]));
#pragma unroll
            for (int p = 0; p < 4; p++) {
                unsigned b0, b1, b2, b3;
                ldsm4(b0, b1, b2, b3,
                      s2u(&Ks[(p * 16 + rowB) * FST + ks * 8 + colB]));
#pragma unroll
                for (int mt = 0; mt < 2; mt++) {
                    mma_tf32(sc[mt][2 * p],     a[mt], b0, b1);
                    mma_tf32(sc[mt][2 * p + 1], a[mt], b2, b3);
                }
            }
        }

        // ---- softmax ----
#pragma unroll
        for (int mt = 0; mt < 2; mt++) {
            const int rlo = q0 + wb + mt * 16 + g;
            const int rhi = rlo + 8;
            const bool need_mask = (k0 + 63 > rlo);
            float rmax0 = -1e30f, rmax1 = -1e30f;
#pragma unroll
            for (int nt = 0; nt < 8; nt++) {
#pragma unroll
                for (int c2 = 0; c2 < 2; c2++) {
                    float v0 = sc[mt][nt][c2    ] * 0.125f;
                    float v1 = sc[mt][nt][c2 + 2] * 0.125f;
                    if (need_mask) {
                        int kj = k0 + nt * 8 + 2 * t + c2;
                        if (kj > rlo) v0 = -1e30f;
                        if (kj > rhi) v1 = -1e30f;
                    }
                    sc[mt][nt][c2    ] = v0;
                    sc[mt][nt][c2 + 2] = v1;
                    rmax0 = fmaxf(rmax0, v0);
                    rmax1 = fmaxf(rmax1, v1);
                }
            }
            rmax0 = fmaxf(rmax0, __shfl_xor_sync(0xffffffffu, rmax0, 1));
            rmax0 = fmaxf(rmax0, __shfl_xor_sync(0xffffffffu, rmax0, 2));
            rmax1 = fmaxf(rmax1, __shfl_xor_sync(0xffffffffu, rmax1, 1));
            rmax1 = fmaxf(rmax1, __shfl_xor_sync(0xffffffffu, rmax1, 2));

            float mn0 = fmaxf(m[mt * 2],     rmax0);
            float mn1 = fmaxf(m[mt * 2 + 1], rmax1);
            float corr0 = __expf(m[mt * 2]     - mn0);
            float corr1 = __expf(m[mt * 2 + 1] - mn1);
            m[mt * 2] = mn0; m[mt * 2 + 1] = mn1;

            float ls0 = 0.f, ls1 = 0.f;
#pragma unroll
            for (int nt = 0; nt < 8; nt++) {
#pragma unroll
                for (int c2 = 0; c2 < 2; c2++) {
                    float p0 = __expf(sc[mt][nt][c2    ] - mn0);
                    float p1 = __expf(sc[mt][nt][c2 + 2] - mn1);
                    ls0 += p0; ls1 += p1;
                    int jj = nt * 8 + 2 * t + c2;
                    Ps[(wb + mt * 16 + g    ) * FST + jj] = f2tf32(p0);
                    Ps[(wb + mt * 16 + g + 8) * FST + jj] = f2tf32(p1);
                }
            }
            ls0 += __shfl_xor_sync(0xffffffffu, ls0, 1);
            ls0 += __shfl_xor_sync(0xffffffffu, ls0, 2);
            ls1 += __shfl_xor_sync(0xffffffffu, ls1, 1);
            ls1 += __shfl_xor_sync(0xffffffffu, ls1, 2);
            l[mt * 2]     = l[mt * 2]     * corr0 + ls0;
            l[mt * 2 + 1] = l[mt * 2 + 1] * corr1 + ls1;

#pragma unroll
            for (int nt = 0; nt < 8; nt++) {
                acc[mt][nt][0] *= corr0; acc[mt][nt][1] *= corr0;
                acc[mt][nt][2] *= corr1; acc[mt][nt][3] *= corr1;
            }
        }

        __syncwarp();

        // ---- acc += P V ----
#pragma unroll
        for (int ks = 0; ks < 8; ks++) {
            unsigned a[2][4];
#pragma unroll
            for (int mt = 0; mt < 2; mt++)
                ldsm4(a[mt][0], a[mt][1], a[mt][2], a[mt][3],
                      s2u(&Ps[(wb + mt * 16 + rowA) * FST + ks * 8 + colA]));
#pragma unroll
            for (int p = 0; p < 4; p++) {
                unsigned b0, b1, b2, b3;
                ldsm4(b0, b1, b2, b3,
                      s2u(&Vt[(p * 16 + rowB) * FST + ks * 8 + colB]));
#pragma unroll
                for (int mt = 0; mt < 2; mt++) {
                    mma_tf32(acc[mt][2 * p],     a[mt], b0, b1);
                    mma_tf32(acc[mt][2 * p + 1], a[mt], b2, b3);
                }
            }
        }
    }

    // Epilogue (tf32-rounded)
#pragma unroll
    for (int mt = 0; mt < 2; mt++) {
        float inv0 = 1.f / l[mt * 2];
        float inv1 = 1.f / l[mt * 2 + 1];
        size_t orow0 = (size_t)(b * Sq + q0 + wb + mt * 16 + g) * QC;
        size_t orow1 = orow0 + 8 * (size_t)QC;
#pragma unroll
        for (int nt = 0; nt < 8; nt++) {
            int col = h * DH + nt * 8 + 2 * t;
            float2 lo = make_float2(
                __uint_as_float(f2tf32(acc[mt][nt][0] * inv0)),
                __uint_as_float(f2tf32(acc[mt][nt][1] * inv0)));
            float2 hi = make_float2(
                __uint_as_float(f2tf32(acc[mt][nt][2] * inv1)),
                __uint_as_float(f2tf32(acc[mt][nt][3] * inv1)));
            *(float2*)&O[orow0 + col] = lo;
            *(float2*)&O[orow1 + col] = hi;
        }
    }
}

// ---------------------------------------------------------------------------
// kernel_launch
// ---------------------------------------------------------------------------
extern "C" void kernel_launch(void* const* d_in, const int* in_sizes, int n_in,
                              void* d_out, int out_size)
{
    const float* hidden = (const float*)d_in[0];
    const float* cosb   = (const float*)d_in[1];
    const float* sinb   = (const float*)d_in[2];
    const float* Wq     = (const float*)d_in[4];
    const float* Wk     = (const float*)d_in[5];
    const float* Wv     = (const float*)d_in[6];
    const float* Wo     = (const float*)d_in[7];
    float* out = (float*)d_out;

    float *Qb, *Kb, *Vb, *Ob;
    unsigned *h32, *wq32, *wk32, *wv32, *wo32, *vt32;
    cudaGetSymbolAddress((void**)&Qb, g_Q);
    cudaGetSymbolAddress((void**)&Kb, g_K);
    cudaGetSymbolAddress((void**)&Vb, g_V);
    cudaGetSymbolAddress((void**)&Ob, g_O);
    cudaGetSymbolAddress((void**)&h32,  g_h32);
    cudaGetSymbolAddress((void**)&wq32, g_wq32);
    cudaGetSymbolAddress((void**)&wk32, g_wk32);
    cudaGetSymbolAddress((void**)&wv32, g_wv32);
    cudaGetSymbolAddress((void**)&wo32, g_wo32);
    cudaGetSymbolAddress((void**)&vt32, g_Vt32);

    // Pre-convert inputs to tf32 bit patterns (5 launches)
    {
        struct { const float* s; unsigned* d; size_t n; } jobs[5] = {
            { hidden, h32,  (size_t)ROWS * Dm },
            { Wq,     wq32, (size_t)QC * Dm },
            { Wk,     wk32, (size_t)KC * Dm },
            { Wv,     wv32, (size_t)KC * Dm },
            { Wo,     wo32, (size_t)Dm * Dm },
        };
        for (int j = 0; j < 5; j++) {
            int n4 = (int)(jobs[j].n / 4);
            cvt_tf32_kernel<<<(n4 + 255) / 256, 256>>>(
                (const float4*)jobs[j].s, (uint4*)jobs[j].d, n4);
        }
    }

    // Fused QKV projections (3-stage BK=16 cp.async, 64x64 warp tiles)
    cudaFuncSetAttribute(qkv_gemm,
        cudaFuncAttributeMaxDynamicSharedMemorySize, GEMM_SMEM_BYTES);
    qkv_gemm<<<dim3(24, ROWS / 128), GEMM_THREADS, GEMM_SMEM_BYTES>>>(
        h32, wq32, wk32, wv32, Qb, Kb, Vb);

    // RoPE on Q and K (single merged launch)
    {
        int total = PQ + PK;
        rope_both_kernel<<<(total + 255) / 256, 256>>>(Qb, Kb, cosb, sinb);
    }

    // Transpose V to [KC][Sq], tf32
    transpose_v_kernel<<<dim3(Sq / 32, KC / 32, Bsz), dim3(32, 8)>>>(Vb, vt32);

    // Flash attention (tf32, double-buffered cp.async K/V)
    {
        int smem_bytes = FLASH_SMEM_WORDS * (int)sizeof(unsigned);  // 208896
        cudaFuncSetAttribute(flash_kernel,
            cudaFuncAttributeMaxDynamicSharedMemorySize, smem_bytes);
        dim3 grid(Sq / QT, Hh, Bsz);
        flash_kernel<<<grid, 256, smem_bytes>>>(
            (const unsigned*)Qb, (const unsigned*)Kb, vt32, Ob);
    }

    // Output projection
    cudaFuncSetAttribute(out_gemm,
        cudaFuncAttributeMaxDynamicSharedMemorySize, GEMM_SMEM_BYTES);
    out_gemm<<<dim3(Dm / 128, ROWS / 128), GEMM_THREADS, GEMM_SMEM_BYTES>>>(
        (const unsigned*)Ob, wo32, out);
}